// round 1
// baseline (speedup 1.0000x reference)
#include <cuda_runtime.h>
#include <stdint.h>

#define B_ 256
#define R_ 192
#define C_ 96
#define O_ 16
#define I_ 20

// Scratch (allocation-free rule: __device__ globals)
__device__ float g_uhat[(size_t)R_ * C_ * B_ * O_];   // [R][C][B][O]  ~302MB
__device__ float g_v[(size_t)B_ * C_ * O_];           // [B][C][O]
__device__ float g_b[R_ * C_];                        // routing logits
__device__ float g_c[R_ * C_];                        // softmax coefficients

// ---- packed fp32x2 helpers (Blackwell dual-FMA pipe, PTX-only) ----
__device__ __forceinline__ unsigned long long pack2(float v) {
    unsigned long long r;
    asm("mov.b64 %0, {%1, %1};" : "=l"(r) : "f"(v));
    return r;
}
__device__ __forceinline__ void fma2(unsigned long long& d, unsigned long long a,
                                     unsigned long long b) {
    asm("fma.rn.f32x2 %0, %1, %2, %3;" : "=l"(d) : "l"(a), "l"(b), "l"(d));
}

__global__ void zero_b_kernel() {
    int i = blockIdx.x * blockDim.x + threadIdx.x;
    if (i < R_ * C_) g_b[i] = 0.f;
}

// ============================================================================
// u_hat[r][c][b][o] = sum_i W[r,c,o,i] * x[b,r,i]
// Block: one r, 8 c's. 256 threads = one b each. W transposed into smem
// so (o,o+1) pairs are adjacent -> LDS.64 broadcast + fma.rn.f32x2.
// ============================================================================
#define CPB 8
__global__ void uhat_kernel(const float* __restrict__ x, const float* __restrict__ W) {
    const int r  = blockIdx.x / (C_ / CPB);
    const int c0 = (blockIdx.x % (C_ / CPB)) * CPB;
    __shared__ __align__(16) float sW[CPB][I_][O_];  // [cc][i][o]
    const int tid = threadIdx.x;

    for (int idx = tid; idx < CPB * O_ * I_; idx += 256) {
        int cc  = idx / (O_ * I_);
        int rem = idx % (O_ * I_);
        int o = rem / I_;
        int i = rem % I_;
        sW[cc][i][o] = W[(((size_t)r * C_ + c0 + cc) * O_ + o) * I_ + i];
    }
    __syncthreads();

    const int b = tid;
    float xr[I_];
    const float4* xp = reinterpret_cast<const float4*>(x + ((size_t)b * R_ + r) * I_);
#pragma unroll
    for (int q = 0; q < 5; q++) {
        float4 t = xp[q];
        xr[4 * q + 0] = t.x; xr[4 * q + 1] = t.y;
        xr[4 * q + 2] = t.z; xr[4 * q + 3] = t.w;
    }

    for (int cc = 0; cc < CPB; cc++) {
        unsigned long long acc[O_ / 2];
#pragma unroll
        for (int op = 0; op < O_ / 2; op++) acc[op] = 0ULL;
#pragma unroll
        for (int i = 0; i < I_; i++) {
            unsigned long long x2 = pack2(xr[i]);
#pragma unroll
            for (int op = 0; op < O_ / 2; op++) {
                unsigned long long w2 =
                    *reinterpret_cast<const unsigned long long*>(&sW[cc][i][2 * op]);
                fma2(acc[op], w2, x2);
            }
        }
        unsigned long long* outp = reinterpret_cast<unsigned long long*>(
            g_uhat + (((size_t)r * C_ + c0 + cc) * B_ + b) * O_);
#pragma unroll
        for (int op = 0; op < O_ / 2; op++) outp[op] = acc[op];
    }
}

// ============================================================================
// c[r,c] = softmax over r of b[r,c].  One block per c, 192 threads (= R).
// ============================================================================
__global__ void softmax_kernel() {
    const int c = blockIdx.x;
    const int tid = threadIdx.x;           // = r
    const int lane = tid & 31, warp = tid >> 5;
    float v = g_b[tid * C_ + c];

    float m = v;
#pragma unroll
    for (int ofs = 16; ofs; ofs >>= 1) m = fmaxf(m, __shfl_xor_sync(0xFFFFFFFFu, m, ofs));
    __shared__ float sm[6], ssum[6];
    if (lane == 0) sm[warp] = m;
    __syncthreads();
    float mm = sm[0];
#pragma unroll
    for (int w = 1; w < 6; w++) mm = fmaxf(mm, sm[w]);

    float e = expf(v - mm);
    float s = e;
#pragma unroll
    for (int ofs = 16; ofs; ofs >>= 1) s += __shfl_xor_sync(0xFFFFFFFFu, s, ofs);
    if (lane == 0) ssum[warp] = s;
    __syncthreads();
    float tot = 0.f;
#pragma unroll
    for (int w = 0; w < 6; w++) tot += ssum[w];

    g_c[tid * C_ + c] = e / tot;
}

// ============================================================================
// s[b,c,o] = sum_r c[r,c] * u_hat[r,c,b,o]; then squash -> v (or d_out).
// One block per (c,b), 192 threads: thread = (g in 0..11, o in 0..15),
// each sums 16 r's (r = g + 12k).
// ============================================================================
__global__ void s_squash_kernel(float* __restrict__ out, int is_final) {
    const int c = blockIdx.x / B_;
    const int b = blockIdx.x % B_;
    const int tid = threadIdx.x;
    const int o = tid & 15, g = tid >> 4;

    float acc = 0.f;
#pragma unroll
    for (int k = 0; k < 16; k++) {
        int r = g + 12 * k;
        float cv = g_c[r * C_ + c];
        acc += cv * g_uhat[(((size_t)r * C_ + c) * B_ + b) * O_ + o];
    }
    __shared__ float ss[12][16];
    ss[g][o] = acc;
    __syncthreads();

    if (tid < 16) {
        float s = 0.f;
#pragma unroll
        for (int gg = 0; gg < 12; gg++) s += ss[gg][tid];
        float n2 = s * s;
#pragma unroll
        for (int ofs = 8; ofs; ofs >>= 1) n2 += __shfl_xor_sync(0xFFFFu, n2, ofs);
        float norm = sqrtf(n2);
        float scale = norm / (1.f + n2);   // squash: (n2/(1+n2)) * s/norm
        float* dst = is_final ? out : g_v;
        dst[((size_t)b * C_ + c) * O_ + tid] = s * scale;
    }
}

// ============================================================================
// a[r,c] = (1/B) sum_{b,o} u_hat[r,c,b,o] * v[b,c,o];  b_ij += a.
// One block per (8 r's, c). v cached in smem (stride 17: conflict-free).
// ============================================================================
#define RPB 8
__global__ void agreement_kernel() {
    const int c  = blockIdx.x % C_;
    const int r0 = (blockIdx.x / C_) * RPB;
    const int tid = threadIdx.x;           // 256
    const int lane = tid & 31, warp = tid >> 5;

    __shared__ float sv[B_ * 17];
    for (int idx = tid; idx < B_ * O_; idx += 256) {
        int bb = idx >> 4, o = idx & 15;
        sv[bb * 17 + o] = g_v[((size_t)bb * C_ + c) * O_ + o];
    }
    __syncthreads();

    const int b = tid;
    float vv[O_];
#pragma unroll
    for (int o = 0; o < O_; o++) vv[o] = sv[b * 17 + o];

    float part[RPB];
#pragma unroll
    for (int rr = 0; rr < RPB; rr++) {
        int r = r0 + rr;
        const float4* up = reinterpret_cast<const float4*>(
            g_uhat + (((size_t)r * C_ + c) * B_ + b) * O_);
        float p = 0.f;
#pragma unroll
        for (int q = 0; q < 4; q++) {
            float4 u = up[q];
            p += u.x * vv[4 * q] + u.y * vv[4 * q + 1] +
                 u.z * vv[4 * q + 2] + u.w * vv[4 * q + 3];
        }
        part[rr] = p;
    }

    __shared__ float red[RPB][8];
#pragma unroll
    for (int rr = 0; rr < RPB; rr++) {
        float p = part[rr];
#pragma unroll
        for (int ofs = 16; ofs; ofs >>= 1) p += __shfl_xor_sync(0xFFFFFFFFu, p, ofs);
        if (lane == 0) red[rr][warp] = p;
    }
    __syncthreads();

    if (tid < RPB) {
        float t = 0.f;
#pragma unroll
        for (int w = 0; w < 8; w++) t += red[tid][w];
        g_b[(r0 + tid) * C_ + c] += t * (1.f / B_);
    }
}

extern "C" void kernel_launch(void* const* d_in, const int* in_sizes, int n_in,
                              void* d_out, int out_size) {
    const float* x = (const float*)d_in[0];  // [B,R,I]
    const float* W = (const float*)d_in[1];  // [R,C,O,I]
    float* out = (float*)d_out;              // [B,C,O]

    zero_b_kernel<<<(R_ * C_ + 255) / 256, 256>>>();
    uhat_kernel<<<R_ * (C_ / CPB), 256>>>(x, W);

    for (int it = 0; it < 3; it++) {
        softmax_kernel<<<C_, 192>>>();
        s_squash_kernel<<<C_ * B_, 192>>>(out, it == 2 ? 1 : 0);
        if (it < 2) agreement_kernel<<<(R_ / RPB) * C_, 256>>>();
    }
}

// round 2
// speedup vs baseline: 1.8112x; 1.8112x over previous
#include <cuda_runtime.h>
#include <cuda_fp16.h>
#include <stdint.h>

#define B_ 256
#define R_ 192
#define C_ 96
#define O_ 16
#define I_ 20

// Scratch (allocation-free rule: __device__ globals)
__device__ __half g_uhat[(size_t)R_ * C_ * B_ * O_];  // [R][C][B][O] fp16 ~151MB
__device__ float  g_xT[(size_t)R_ * I_ * B_];         // [R][I][B] transposed x
__device__ float  g_v[(size_t)B_ * C_ * O_];          // [B][C][O]
__device__ float  g_b[R_ * C_];                       // routing logits
__device__ float  g_c[R_ * C_];                       // softmax coefficients

// ---- packed fp32x2 helpers (Blackwell dual-FMA pipe, PTX-only) ----
__device__ __forceinline__ unsigned long long pack2(float v) {
    unsigned long long r;
    asm("mov.b64 %0, {%1, %1};" : "=l"(r) : "f"(v));
    return r;
}
__device__ __forceinline__ void fma2(unsigned long long& d, unsigned long long a,
                                     unsigned long long b) {
    asm("fma.rn.f32x2 %0, %1, %2, %3;" : "=l"(d) : "l"(a), "l"(b), "l"(d));
}
__device__ __forceinline__ float2 unpack2(unsigned long long v) {
    float2 f;
    asm("mov.b64 {%0, %1}, %2;" : "=f"(f.x), "=f"(f.y) : "l"(v));
    return f;
}

__global__ void zero_b_kernel() {
    int i = blockIdx.x * blockDim.x + threadIdx.x;
    if (i < R_ * C_) g_b[i] = 0.f;
}

// ============================================================================
// Transpose x[b][r][i] -> xT[r][i][b]. block = r (192), thread = b (256).
// Reads are thread-contiguous (L1-served), writes are coalesced over b.
// ============================================================================
__global__ void xpose_kernel(const float* __restrict__ x) {
    const int r = blockIdx.x;
    const int b = threadIdx.x;
    float t[I_];
#pragma unroll
    for (int q = 0; q < 5; q++) {
        float4 v = reinterpret_cast<const float4*>(x + ((size_t)b * R_ + r) * I_)[q];
        t[4 * q + 0] = v.x; t[4 * q + 1] = v.y; t[4 * q + 2] = v.z; t[4 * q + 3] = v.w;
    }
#pragma unroll
    for (int i = 0; i < I_; i++)
        g_xT[((size_t)r * I_ + i) * B_ + b] = t[i];
}

// ============================================================================
// u_hat[r][c][b][o] = sum_i W[r,c,o,i] * x[b,r,i]  (fp32 compute, fp16 store)
// Block: one r, 8 c's. 128 threads; each thread handles b = tid and tid+128
// so every broadcast W smem load feeds TWO fma.rn.f32x2.
// ============================================================================
#define CPB 8
__global__ void __launch_bounds__(128) uhat_kernel(const float* __restrict__ W) {
    const int r  = blockIdx.x / (C_ / CPB);
    const int c0 = (blockIdx.x % (C_ / CPB)) * CPB;
    __shared__ __align__(16) float sW[CPB][I_][O_];  // [cc][i][o]
    const int tid = threadIdx.x;

    for (int idx = tid; idx < CPB * O_ * I_; idx += 128) {
        int cc  = idx / (O_ * I_);
        int rem = idx % (O_ * I_);
        int o = rem / I_;
        int i = rem % I_;
        sW[cc][i][o] = W[(((size_t)r * C_ + c0 + cc) * O_ + o) * I_ + i];
    }

    // coalesced x loads from transposed layout
    float xr[2][I_];
#pragma unroll
    for (int i = 0; i < I_; i++) {
        xr[0][i] = g_xT[((size_t)r * I_ + i) * B_ + tid];
        xr[1][i] = g_xT[((size_t)r * I_ + i) * B_ + tid + 128];
    }
    __syncthreads();

    for (int cc = 0; cc < CPB; cc++) {
        unsigned long long acc[2][O_ / 2];
#pragma unroll
        for (int h = 0; h < 2; h++)
#pragma unroll
            for (int op = 0; op < O_ / 2; op++) acc[h][op] = 0ULL;

#pragma unroll
        for (int i = 0; i < I_; i++) {
            unsigned long long x20 = pack2(xr[0][i]);
            unsigned long long x21 = pack2(xr[1][i]);
#pragma unroll
            for (int op = 0; op < O_ / 2; op++) {
                unsigned long long w2 =
                    *reinterpret_cast<const unsigned long long*>(&sW[cc][i][2 * op]);
                fma2(acc[0][op], w2, x20);
                fma2(acc[1][op], w2, x21);
            }
        }
#pragma unroll
        for (int h = 0; h < 2; h++) {
            const int b = tid + h * 128;
            __half2 hv[O_ / 2];
#pragma unroll
            for (int op = 0; op < O_ / 2; op++) {
                float2 f = unpack2(acc[h][op]);
                hv[op] = __floats2half2_rn(f.x, f.y);
            }
            uint4* dst = reinterpret_cast<uint4*>(
                g_uhat + (((size_t)r * C_ + c0 + cc) * B_ + b) * O_);
            dst[0] = *reinterpret_cast<uint4*>(&hv[0]);
            dst[1] = *reinterpret_cast<uint4*>(&hv[4]);
        }
    }
}

// ============================================================================
// c[r,c] = softmax over r of b[r,c].  One block per c, 192 threads (= R).
// ============================================================================
__global__ void softmax_kernel() {
    const int c = blockIdx.x;
    const int tid = threadIdx.x;           // = r
    const int lane = tid & 31, warp = tid >> 5;
    float v = g_b[tid * C_ + c];

    float m = v;
#pragma unroll
    for (int ofs = 16; ofs; ofs >>= 1) m = fmaxf(m, __shfl_xor_sync(0xFFFFFFFFu, m, ofs));
    __shared__ float sm[6], ssum[6];
    if (lane == 0) sm[warp] = m;
    __syncthreads();
    float mm = sm[0];
#pragma unroll
    for (int w = 1; w < 6; w++) mm = fmaxf(mm, sm[w]);

    float e = expf(v - mm);
    float s = e;
#pragma unroll
    for (int ofs = 16; ofs; ofs >>= 1) s += __shfl_xor_sync(0xFFFFFFFFu, s, ofs);
    if (lane == 0) ssum[warp] = s;
    __syncthreads();
    float tot = 0.f;
#pragma unroll
    for (int w = 0; w < 6; w++) tot += ssum[w];

    g_c[tid * C_ + c] = e / tot;
}

// ============================================================================
// s[b,c,o] = sum_r c[r,c] * u_hat[r,c,b,o]; then squash -> v (or d_out).
// Block = (c, 32-b chunk). 256 threads = (b_local = tid>>3, o-pair = tid&7).
// Each thread streams one half2 per r: warp load = 128B contiguous.
// ============================================================================
__global__ void s_squash_kernel(float* __restrict__ out, int is_final) {
    const int c  = blockIdx.x >> 3;
    const int b0 = (blockIdx.x & 7) * 32;
    const int tid = threadIdx.x;

    __shared__ float sc[R_];
    for (int rr = tid; rr < R_; rr += 256) sc[rr] = g_c[rr * C_ + c];
    __syncthreads();

    const int bl = tid >> 3, op = tid & 7;
    const __half2* base = reinterpret_cast<const __half2*>(g_uhat)
                        + ((size_t)c * B_ + b0 + bl) * 8 + op;
    const size_t stride = (size_t)C_ * B_ * 8;  // per-r stride in half2

    float2 acc = make_float2(0.f, 0.f);
#pragma unroll 8
    for (int r = 0; r < R_; r++) {
        float2 u = __half22float2(base[(size_t)r * stride]);
        float cv = sc[r];
        acc.x = fmaf(cv, u.x, acc.x);
        acc.y = fmaf(cv, u.y, acc.y);
    }

    // squash: norm over the 16 o's held by 8 consecutive lanes (same b)
    float n2 = acc.x * acc.x + acc.y * acc.y;
#pragma unroll
    for (int ofs = 1; ofs < 8; ofs <<= 1) n2 += __shfl_xor_sync(0xFFFFFFFFu, n2, ofs);
    float scale = sqrtf(n2) / (1.f + n2);

    float* dst = is_final ? out : g_v;
    float2* p = reinterpret_cast<float2*>(dst + ((size_t)(b0 + bl) * C_ + c) * O_) + op;
    *p = make_float2(acc.x * scale, acc.y * scale);
}

// ============================================================================
// a[r,c] = (1/B) sum_{b,o} u_hat[r,c,b,o] * v[b,c,o];  b_ij += a.
// One block per (8 r's, c). 256 threads = b. u_hat read as 2x uint4 (fp16).
// ============================================================================
#define RPB 8
__global__ void agreement_kernel() {
    const int c  = blockIdx.x % C_;
    const int r0 = (blockIdx.x / C_) * RPB;
    const int tid = threadIdx.x;           // 256
    const int lane = tid & 31, warp = tid >> 5;

    __shared__ float sv[B_ * 17];
    for (int idx = tid; idx < B_ * O_; idx += 256) {
        int bb = idx >> 4, o = idx & 15;
        sv[bb * 17 + o] = g_v[((size_t)bb * C_ + c) * O_ + o];
    }
    __syncthreads();

    const int b = tid;
    float vv[O_];
#pragma unroll
    for (int o = 0; o < O_; o++) vv[o] = sv[b * 17 + o];

    float part[RPB];
#pragma unroll
    for (int rr = 0; rr < RPB; rr++) {
        int r = r0 + rr;
        const uint4* up = reinterpret_cast<const uint4*>(
            g_uhat + (((size_t)r * C_ + c) * B_ + b) * O_);
        uint4 u0 = up[0], u1 = up[1];
        const __half2* h0 = reinterpret_cast<const __half2*>(&u0);
        const __half2* h1 = reinterpret_cast<const __half2*>(&u1);
        float p = 0.f;
#pragma unroll
        for (int q = 0; q < 4; q++) {
            float2 a = __half22float2(h0[q]);
            p = fmaf(a.x, vv[2 * q], p);
            p = fmaf(a.y, vv[2 * q + 1], p);
            float2 bb2 = __half22float2(h1[q]);
            p = fmaf(bb2.x, vv[8 + 2 * q], p);
            p = fmaf(bb2.y, vv[8 + 2 * q + 1], p);
        }
        part[rr] = p;
    }

    __shared__ float red[RPB][8];
#pragma unroll
    for (int rr = 0; rr < RPB; rr++) {
        float p = part[rr];
#pragma unroll
        for (int ofs = 16; ofs; ofs >>= 1) p += __shfl_xor_sync(0xFFFFFFFFu, p, ofs);
        if (lane == 0) red[rr][warp] = p;
    }
    __syncthreads();

    if (tid < RPB) {
        float t = 0.f;
#pragma unroll
        for (int w = 0; w < 8; w++) t += red[tid][w];
        g_b[(r0 + tid) * C_ + c] += t * (1.f / B_);
    }
}

extern "C" void kernel_launch(void* const* d_in, const int* in_sizes, int n_in,
                              void* d_out, int out_size) {
    const float* x = (const float*)d_in[0];  // [B,R,I]
    const float* W = (const float*)d_in[1];  // [R,C,O,I]
    float* out = (float*)d_out;              // [B,C,O]

    zero_b_kernel<<<(R_ * C_ + 255) / 256, 256>>>();
    xpose_kernel<<<R_, 256>>>(x);
    uhat_kernel<<<R_ * (C_ / CPB), 128>>>(W);

    for (int it = 0; it < 3; it++) {
        softmax_kernel<<<C_, 192>>>();
        s_squash_kernel<<<C_ * 8, 256>>>(out, it == 2 ? 1 : 0);
        if (it < 2) agreement_kernel<<<(R_ / RPB) * C_, 256>>>();
    }
}